// round 1
// baseline (speedup 1.0000x reference)
#include <cuda_runtime.h>
#include <math.h>

// ---------------------------------------------------------------------------
// Problem constants (B=2, N=2048, C=1024, H=16, R1=4, R2=8, HEAD_DIM=64)
// ---------------------------------------------------------------------------
#define BATCH 2
#define SEQ   2048
#define CH    1024
#define NH    16
#define RR1   4
#define RR2   8
#define HD    64
#define RKD   32              // R1*R2: effective qk head dim
#define MROWS (BATCH*SEQ)     // 4096

__device__ __constant__ float kSCALE = 0.17677669529663687f; // (R1*R2)^-0.5

// ---------------------------------------------------------------------------
// Scratch (device globals; no allocation allowed)
// ---------------------------------------------------------------------------
__device__ float g_q1[MROWS * NH * RR1];
__device__ float g_k1[MROWS * NH * RR1];
__device__ float g_q2[MROWS * NH * RR2];
__device__ float g_k2[MROWS * NH * RR2];
__device__ float g_v [MROWS * CH];
__device__ float g_qk[(size_t)BATCH * NH * SEQ * RKD];
__device__ float g_kk[(size_t)BATCH * NH * SEQ * RKD];
__device__ float g_ao[MROWS * CH];

// ---------------------------------------------------------------------------
// NT SGEMM: C[M,Nc] = A[M,K] @ B[Nc,K]^T (+bias). Both A and B K-major.
// BM=BN=64, BK=16, 256 threads, 4x4 micro-tile per thread.
// All dims here are multiples of the tile sizes (M=4096, Nc in {64,128,1024},
// K=1024), so no edge guards.
// ---------------------------------------------------------------------------
#define GBM 64
#define GBN 64
#define GBK 16

__global__ __launch_bounds__(256)
void gemm_nt_kernel(const float* __restrict__ A, const float* __restrict__ Bm,
                    const float* __restrict__ bias, float* __restrict__ Cm,
                    int M, int Nc, int K)
{
    __shared__ float As[GBK][GBM];
    __shared__ float Bs[GBK][GBN];

    const int tid = threadIdx.x;
    const int m0 = blockIdx.x * GBM;
    const int n0 = blockIdx.y * GBN;

    const int lr = tid >> 2;          // 0..63 row within tile
    const int lc = (tid & 3) * 4;     // 0,4,8,12 col within k-slab

    const int tx = tid & 15;          // 0..15 -> 4 cols each
    const int ty = tid >> 4;          // 0..15 -> 4 rows each

    float acc[4][4] = {};

    for (int k0 = 0; k0 < K; k0 += GBK) {
        const float4 av = *reinterpret_cast<const float4*>(&A[(size_t)(m0 + lr) * K + k0 + lc]);
        const float4 bv = *reinterpret_cast<const float4*>(&Bm[(size_t)(n0 + lr) * K + k0 + lc]);
        __syncthreads();
        As[lc + 0][lr] = av.x; As[lc + 1][lr] = av.y;
        As[lc + 2][lr] = av.z; As[lc + 3][lr] = av.w;
        Bs[lc + 0][lr] = bv.x; Bs[lc + 1][lr] = bv.y;
        Bs[lc + 2][lr] = bv.z; Bs[lc + 3][lr] = bv.w;
        __syncthreads();

        #pragma unroll
        for (int kk = 0; kk < GBK; kk++) {
            float ar[4], br[4];
            #pragma unroll
            for (int i = 0; i < 4; i++) ar[i] = As[kk][ty * 4 + i];
            #pragma unroll
            for (int j = 0; j < 4; j++) br[j] = Bs[kk][tx * 4 + j];
            #pragma unroll
            for (int i = 0; i < 4; i++)
                #pragma unroll
                for (int j = 0; j < 4; j++)
                    acc[i][j] = fmaf(ar[i], br[j], acc[i][j]);
        }
    }

    #pragma unroll
    for (int i = 0; i < 4; i++) {
        const int m = m0 + ty * 4 + i;
        #pragma unroll
        for (int j = 0; j < 4; j++) {
            const int n = n0 + tx * 4 + j;
            float v = acc[i][j];
            if (bias) v += bias[n];
            Cm[(size_t)m * Nc + n] = v;
        }
    }
}

// ---------------------------------------------------------------------------
// Form qk = outer(q1,q2)*SCALE and kk = outer(k1,k2), head-major layout:
//   g_qk[((b*NH+h)*SEQ + n)*32 + r1*8 + r2]
// One thread per (b,n,h).
// ---------------------------------------------------------------------------
__global__ void form_qkkk_kernel()
{
    const int idx = blockIdx.x * blockDim.x + threadIdx.x;
    if (idx >= MROWS * NH) return;
    const int h  = idx % NH;
    const int bn = idx / NH;            // b*SEQ + n
    const int b  = bn / SEQ;
    const int n  = bn % SEQ;

    float a1[RR1], a2[RR2];
    #pragma unroll
    for (int r = 0; r < RR1; r++) a1[r] = g_q1[(size_t)bn * (NH * RR1) + h * RR1 + r];
    #pragma unroll
    for (int r = 0; r < RR2; r++) a2[r] = g_q2[(size_t)bn * (NH * RR2) + h * RR2 + r];

    float* dq = &g_qk[(((size_t)b * NH + h) * SEQ + n) * RKD];
    #pragma unroll
    for (int r1 = 0; r1 < RR1; r1++)
        #pragma unroll
        for (int r2 = 0; r2 < RR2; r2++)
            dq[r1 * RR2 + r2] = a1[r1] * a2[r2] * kSCALE;

    #pragma unroll
    for (int r = 0; r < RR1; r++) a1[r] = g_k1[(size_t)bn * (NH * RR1) + h * RR1 + r];
    #pragma unroll
    for (int r = 0; r < RR2; r++) a2[r] = g_k2[(size_t)bn * (NH * RR2) + h * RR2 + r];

    float* dk = &g_kk[(((size_t)b * NH + h) * SEQ + n) * RKD];
    #pragma unroll
    for (int r1 = 0; r1 < RR1; r1++)
        #pragma unroll
        for (int r2 = 0; r2 < RR2; r2++)
            dk[r1 * RR2 + r2] = a1[r1] * a2[r2];
}

// ---------------------------------------------------------------------------
// Causal flash attention, fp32. d_qk=32, d_v=64.
// Grid: (SEQ/128, BATCH*NH). Block: 128 threads, 1 query per thread.
// K-tiles of 64 keys staged to smem; scores in padded smem (stride 65).
// ---------------------------------------------------------------------------
#define AQ   128               // queries per block
#define AK   64                // keys per tile
#define SSTR 65                // padded score-row stride (kills bank conflicts)
#define L2E  1.44269504088896341f

#define ATTN_SMEM_FLOATS (AK*RKD + AK*HD + AQ*SSTR)
#define ATTN_SMEM_BYTES  (ATTN_SMEM_FLOATS * 4)

__global__ __launch_bounds__(AQ)
void attn_kernel()
{
    extern __shared__ float sm[];
    float* Ks = sm;                       // [64][32]
    float* Vs = sm + AK * RKD;            // [64][64]
    float* Ss = Vs + AK * HD;             // [128][65]

    const int bh  = blockIdx.y;           // b*NH + h
    const int b   = bh / NH;
    const int h   = bh % NH;
    const int qt  = blockIdx.x;
    const int tid = threadIdx.x;
    const int qi  = qt * AQ + tid;        // global query index

    float q[RKD];
    const float* qrow = &g_qk[((size_t)bh * SEQ + qi) * RKD];
    #pragma unroll
    for (int d = 0; d < RKD; d++) q[d] = qrow[d];

    float o[HD];
    #pragma unroll
    for (int d = 0; d < HD; d++) o[d] = 0.f;
    float mrun = -1e30f, lsum = 0.f;

    const int ktiles = 2 * qt + 2;        // causal: keys up to (qt+1)*128

    for (int kt = 0; kt < ktiles; kt++) {
        const int j0 = kt * AK;

        __syncthreads();   // protect previous tile's Ks/Vs reads
        // stage K tile: 64x32 floats -> 512 float4, 4 per thread
        for (int i = tid; i < AK * RKD / 4; i += AQ) {
            const int row = i >> 3, c = (i & 7) * 4;
            *reinterpret_cast<float4*>(&Ks[row * RKD + c]) =
                *reinterpret_cast<const float4*>(&g_kk[((size_t)bh * SEQ + j0 + row) * RKD + c]);
        }
        // stage V tile: 64x64 floats -> 1024 float4, 8 per thread
        for (int i = tid; i < AK * HD / 4; i += AQ) {
            const int row = i >> 4, c = (i & 15) * 4;
            *reinterpret_cast<float4*>(&Vs[row * HD + c]) =
                *reinterpret_cast<const float4*>(&g_v[((size_t)(b * SEQ + j0 + row)) * CH + h * HD + c]);
        }
        __syncthreads();

        if (j0 <= qi) {
            float* srow = &Ss[tid * SSTR];
            float mt = -1e30f;
            #pragma unroll 4
            for (int j = 0; j < AK; j++) {
                float s = -1e30f;
                if (j0 + j <= qi) {
                    s = 0.f;
                    const float* krow = &Ks[j * RKD];
                    #pragma unroll
                    for (int d = 0; d < RKD; d++) s = fmaf(q[d], krow[d], s);
                }
                srow[j] = s;
                mt = fmaxf(mt, s);
            }
            const float mnew = fmaxf(mrun, mt);
            const float corr = exp2f((mrun - mnew) * L2E);
            lsum *= corr;
            #pragma unroll
            for (int d = 0; d < HD; d++) o[d] *= corr;

            for (int j = 0; j < AK; j++) {
                const float p = exp2f((srow[j] - mnew) * L2E);
                lsum += p;
                const float* vrow = &Vs[j * HD];
                #pragma unroll
                for (int d = 0; d < HD; d++) o[d] = fmaf(p, vrow[d], o[d]);
            }
            mrun = mnew;
        }
    }

    const float inv = 1.f / lsum;
    float* dst = &g_ao[((size_t)(b * SEQ + qi)) * CH + h * HD];
    #pragma unroll
    for (int d = 0; d < HD; d++) dst[d] = o[d] * inv;
}

// ---------------------------------------------------------------------------
// Launch
// ---------------------------------------------------------------------------
extern "C" void kernel_launch(void* const* d_in, const int* in_sizes, int n_in,
                              void* d_out, int out_size)
{
    const float* x   = (const float*)d_in[0];
    const float* Wq1 = (const float*)d_in[1];
    const float* Wk1 = (const float*)d_in[2];
    const float* Wq2 = (const float*)d_in[3];
    const float* Wk2 = (const float*)d_in[4];
    const float* Wv  = (const float*)d_in[5];
    const float* Wo  = (const float*)d_in[6];
    const float* bo  = (const float*)d_in[7];
    float* out = (float*)d_out;

    // raise dynamic smem cap for the attention kernel (idempotent, not a
    // stream op -> safe under graph capture)
    cudaFuncSetAttribute(attn_kernel, cudaFuncAttributeMaxDynamicSharedMemorySize,
                         ATTN_SMEM_BYTES);

    float* q1; cudaGetSymbolAddress((void**)&q1, g_q1);
    float* k1; cudaGetSymbolAddress((void**)&k1, g_k1);
    float* q2; cudaGetSymbolAddress((void**)&q2, g_q2);
    float* k2; cudaGetSymbolAddress((void**)&k2, g_k2);
    float* v;  cudaGetSymbolAddress((void**)&v,  g_v);
    float* ao; cudaGetSymbolAddress((void**)&ao, g_ao);

    dim3 blk(256);
    // projections
    gemm_nt_kernel<<<dim3(MROWS / GBM, (NH * RR1) / GBN), blk>>>(x, Wq1, nullptr, q1, MROWS, NH * RR1, CH);
    gemm_nt_kernel<<<dim3(MROWS / GBM, (NH * RR1) / GBN), blk>>>(x, Wk1, nullptr, k1, MROWS, NH * RR1, CH);
    gemm_nt_kernel<<<dim3(MROWS / GBM, (NH * RR2) / GBN), blk>>>(x, Wq2, nullptr, q2, MROWS, NH * RR2, CH);
    gemm_nt_kernel<<<dim3(MROWS / GBM, (NH * RR2) / GBN), blk>>>(x, Wk2, nullptr, k2, MROWS, NH * RR2, CH);
    gemm_nt_kernel<<<dim3(MROWS / GBM, CH / GBN), blk>>>(x, Wv, nullptr, v, MROWS, CH, CH);

    // qk / kk outer products
    form_qkkk_kernel<<<(MROWS * NH + 255) / 256, 256>>>();

    // causal flash attention
    attn_kernel<<<dim3(SEQ / AQ, BATCH * NH), AQ, ATTN_SMEM_BYTES>>>();

    // output projection + bias
    gemm_nt_kernel<<<dim3(MROWS / GBM, CH / GBN), blk>>>(ao, Wo, bo, out, MROWS, CH, CH);
}

// round 5
// speedup vs baseline: 1.4577x; 1.4577x over previous
#include <cuda_runtime.h>
#include <cuda_bf16.h>
#include <math.h>
#include <stdint.h>

// ---------------------------------------------------------------------------
// Problem constants (B=2, N=2048, C=1024, H=16, R1=4, R2=8, HEAD_DIM=64)
// ---------------------------------------------------------------------------
#define BATCH 2
#define SEQ   2048
#define CH    1024
#define NH    16
#define RR1   4
#define RR2   8
#define HD    64
#define RKD   32              // R1*R2: effective qk head dim
#define MROWS (BATCH*SEQ)     // 4096
#define PROJC 384             // 64+64+128+128 concatenated projection outputs

__device__ __constant__ float kSCALE = 0.17677669529663687f; // (R1*R2)^-0.5

// ---------------------------------------------------------------------------
// Scratch (device globals; no allocation allowed)
// ---------------------------------------------------------------------------
__device__ __nv_bfloat16 g_xh [MROWS * CH];
__device__ __nv_bfloat16 g_xl [MROWS * CH];
__device__ __nv_bfloat16 g_wch[PROJC * CH];   // concat(Wq1,Wk1,Wq2,Wk2) hi
__device__ __nv_bfloat16 g_wcl[PROJC * CH];   // lo
__device__ __nv_bfloat16 g_wvh[CH * CH];
__device__ __nv_bfloat16 g_wvl[CH * CH];
__device__ __nv_bfloat16 g_woh[CH * CH];
__device__ __nv_bfloat16 g_wol[CH * CH];
__device__ __nv_bfloat16 g_aoh[MROWS * CH];
__device__ __nv_bfloat16 g_aol[MROWS * CH];

__device__ float g_proj[MROWS * PROJC];
__device__ float g_v  [MROWS * CH];
__device__ float g_qk [(size_t)BATCH * NH * SEQ * RKD];
__device__ float g_kk [(size_t)BATCH * NH * SEQ * RKD];
__device__ float g_ao [MROWS * CH];

// ---------------------------------------------------------------------------
// Warp-MMA helpers (portable tensor-core path: sm_80+, works on sm_100 plain)
// ---------------------------------------------------------------------------
__device__ __forceinline__ uint32_t smem_u32(const void* p) {
    uint32_t a;
    asm("{ .reg .u64 t; cvta.to.shared.u64 t, %1; cvt.u32.u64 %0, t; }"
        : "=r"(a) : "l"(p));
    return a;
}

__device__ __forceinline__ void ldsm_x4(uint32_t addr, uint32_t& r0, uint32_t& r1,
                                        uint32_t& r2, uint32_t& r3) {
    asm volatile("ldmatrix.sync.aligned.m8n8.x4.shared.b16 {%0,%1,%2,%3}, [%4];"
                 : "=r"(r0), "=r"(r1), "=r"(r2), "=r"(r3) : "r"(addr));
}

__device__ __forceinline__ void mma16816(float* c, uint32_t a0, uint32_t a1,
                                         uint32_t a2, uint32_t a3,
                                         uint32_t b0, uint32_t b1) {
    asm volatile(
        "mma.sync.aligned.m16n8k16.row.col.f32.bf16.bf16.f32 "
        "{%0,%1,%2,%3}, {%4,%5,%6,%7}, {%8,%9}, {%0,%1,%2,%3};"
        : "+f"(c[0]), "+f"(c[1]), "+f"(c[2]), "+f"(c[3])
        : "r"(a0), "r"(a1), "r"(a2), "r"(a3), "r"(b0), "r"(b1));
}

// ---------------------------------------------------------------------------
// Split fp32 -> bf16 hi/lo (Ootomo split for bf16x3 GEMM)
// ---------------------------------------------------------------------------
__global__ void split_kernel(const float* __restrict__ src,
                             __nv_bfloat16* __restrict__ hi,
                             __nv_bfloat16* __restrict__ lo, int n)
{
    int i = blockIdx.x * blockDim.x + threadIdx.x;
    if (i < n) {
        float v = src[i];
        __nv_bfloat16 h = __float2bfloat16(v);
        float r = v - __bfloat162float(h);
        hi[i] = h;
        lo[i] = __float2bfloat16(r);
    }
}

// ---------------------------------------------------------------------------
// bf16x3 NT GEMM via mma.sync: C[M,Nc] = A[M,K] @ B[Nc,K]^T (+bias), fp32 out.
// Block tile 128x128, K-chunk 32. 8 warps, each 64x32 (2x4 warp grid).
// smem rows padded to 40 bf16 (80B) -> 16B-aligned, conflict-free ldmatrix.
// 3 passes per chunk: Ah*Bh, Ah*Bl, Al*Bh (fp32 accumulate).
// ---------------------------------------------------------------------------
#define TM 128
#define TN 128
#define TKC 32
#define GT 256
#define SPAD 40                 // bf16 per smem row (32 + 8 pad)

__global__ __launch_bounds__(GT)
void gemm_bf16x3(const __nv_bfloat16* __restrict__ Ahi,
                 const __nv_bfloat16* __restrict__ Alo,
                 const __nv_bfloat16* __restrict__ Bhi,
                 const __nv_bfloat16* __restrict__ Blo,
                 const float* __restrict__ bias,
                 float* __restrict__ C, int Nc, int K)
{
    __shared__ __nv_bfloat16 sAh[TM * SPAD];
    __shared__ __nv_bfloat16 sAl[TM * SPAD];
    __shared__ __nv_bfloat16 sBh[TN * SPAD];
    __shared__ __nv_bfloat16 sBl[TN * SPAD];

    const int tid  = threadIdx.x;
    const int wid  = tid >> 5;
    const int lane = tid & 31;
    const int wm   = wid >> 2;          // 0..1  (64 rows each)
    const int wn   = wid & 3;           // 0..3  (32 cols each)

    const int m0 = blockIdx.x * TM;
    const int n0 = blockIdx.y * TN;

    float acc[4][4][4] = {};            // [mt][nt][frag]

    // ldmatrix lane addressing (byte offsets within a tile, stride 80B)
    // A: row = lane%16, colgrp = lane/16  (8 bf16 each)
    const int a_r = lane & 15, a_c = (lane >> 4) * 8;
    // B: row = (lane&7) + (lane>>4)*8, colgrp = (lane>>3)&1
    const int b_r = (lane & 7) + ((lane >> 4) << 3), b_c = ((lane >> 3) & 1) * 8;

    const uint32_t sAh_u = smem_u32(sAh), sAl_u = smem_u32(sAl);
    const uint32_t sBh_u = smem_u32(sBh), sBl_u = smem_u32(sBl);

    for (int k0 = 0; k0 < K; k0 += TKC) {
        __syncthreads();
        // stage 4 tiles of 128 rows x 32 bf16 (= 4 x float4 per row)
        #pragma unroll
        for (int i = tid; i < TM * 4; i += GT) {
            const int row = i >> 2, seg = (i & 3) * 8;
            const int so = row * SPAD + seg;
            const size_t ga = (size_t)(m0 + row) * K + k0 + seg;
            const size_t gb = (size_t)(n0 + row) * K + k0 + seg;
            *reinterpret_cast<float4*>(&sAh[so]) = *reinterpret_cast<const float4*>(&Ahi[ga]);
            *reinterpret_cast<float4*>(&sAl[so]) = *reinterpret_cast<const float4*>(&Alo[ga]);
            *reinterpret_cast<float4*>(&sBh[so]) = *reinterpret_cast<const float4*>(&Bhi[gb]);
            *reinterpret_cast<float4*>(&sBl[so]) = *reinterpret_cast<const float4*>(&Blo[gb]);
        }
        __syncthreads();

        #pragma unroll
        for (int kp = 0; kp < 2; kp++) {            // two k16 phases per chunk
            const int kb = kp * 16;
            uint32_t ah[4][4], al[4][4], bh[2][4], bl[2][4];

            #pragma unroll
            for (int mt = 0; mt < 4; mt++) {
                const uint32_t off =
                    (uint32_t)((wm * 64 + mt * 16 + a_r) * SPAD + kb + a_c) * 2;
                ldsm_x4(sAh_u + off, ah[mt][0], ah[mt][1], ah[mt][2], ah[mt][3]);
                ldsm_x4(sAl_u + off, al[mt][0], al[mt][1], al[mt][2], al[mt][3]);
            }
            #pragma unroll
            for (int ng = 0; ng < 2; ng++) {        // n16 groups
                const uint32_t off =
                    (uint32_t)((wn * 32 + ng * 16 + b_r) * SPAD + kb + b_c) * 2;
                ldsm_x4(sBh_u + off, bh[ng][0], bh[ng][1], bh[ng][2], bh[ng][3]);
                ldsm_x4(sBl_u + off, bl[ng][0], bl[ng][1], bl[ng][2], bl[ng][3]);
            }

            #pragma unroll
            for (int mt = 0; mt < 4; mt++) {
                #pragma unroll
                for (int nt = 0; nt < 4; nt++) {
                    const int ng = nt >> 1, hp = (nt & 1) * 2;
                    // hi*hi
                    mma16816(acc[mt][nt], ah[mt][0], ah[mt][1], ah[mt][2], ah[mt][3],
                             bh[ng][hp], bh[ng][hp + 1]);
                    // hi*lo
                    mma16816(acc[mt][nt], ah[mt][0], ah[mt][1], ah[mt][2], ah[mt][3],
                             bl[ng][hp], bl[ng][hp + 1]);
                    // lo*hi
                    mma16816(acc[mt][nt], al[mt][0], al[mt][1], al[mt][2], al[mt][3],
                             bh[ng][hp], bh[ng][hp + 1]);
                }
            }
        }
    }

    // epilogue: c0/c1 at (row lane/4, col (lane%4)*2), c2/c3 at row+8
    const int er = lane >> 2, ec = (lane & 3) * 2;
    #pragma unroll
    for (int mt = 0; mt < 4; mt++) {
        #pragma unroll
        for (int nt = 0; nt < 4; nt++) {
            const int row = m0 + wm * 64 + mt * 16 + er;
            const int col = n0 + wn * 32 + nt * 8 + ec;
            float b0 = bias ? bias[col] : 0.f;
            float b1 = bias ? bias[col + 1] : 0.f;
            C[(size_t)row * Nc + col]           = acc[mt][nt][0] + b0;
            C[(size_t)row * Nc + col + 1]       = acc[mt][nt][1] + b1;
            C[(size_t)(row + 8) * Nc + col]     = acc[mt][nt][2] + b0;
            C[(size_t)(row + 8) * Nc + col + 1] = acc[mt][nt][3] + b1;
        }
    }
}

// ---------------------------------------------------------------------------
// Form qk = outer(q1,q2)*SCALE and kk = outer(k1,k2) from fused projection.
// g_proj layout: [bn][384] = [q1(64) | k1(64) | q2(128) | k2(128)]
// ---------------------------------------------------------------------------
__global__ void form_qkkk_kernel()
{
    const int idx = blockIdx.x * blockDim.x + threadIdx.x;
    if (idx >= MROWS * NH) return;
    const int h  = idx % NH;
    const int bn = idx / NH;
    const int b  = bn / SEQ;
    const int n  = bn % SEQ;

    const float* pr = &g_proj[(size_t)bn * PROJC];
    float a1[RR1], a2[RR2];
    #pragma unroll
    for (int r = 0; r < RR1; r++) a1[r] = pr[h * RR1 + r];
    #pragma unroll
    for (int r = 0; r < RR2; r++) a2[r] = pr[128 + h * RR2 + r];

    float* dq = &g_qk[(((size_t)b * NH + h) * SEQ + n) * RKD];
    #pragma unroll
    for (int r1 = 0; r1 < RR1; r1++)
        #pragma unroll
        for (int r2 = 0; r2 < RR2; r2++)
            dq[r1 * RR2 + r2] = a1[r1] * a2[r2] * kSCALE;

    #pragma unroll
    for (int r = 0; r < RR1; r++) a1[r] = pr[64 + h * RR1 + r];
    #pragma unroll
    for (int r = 0; r < RR2; r++) a2[r] = pr[256 + h * RR2 + r];

    float* dk = &g_kk[(((size_t)b * NH + h) * SEQ + n) * RKD];
    #pragma unroll
    for (int r1 = 0; r1 < RR1; r1++)
        #pragma unroll
        for (int r2 = 0; r2 < RR2; r2++)
            dk[r1 * RR2 + r2] = a1[r1] * a2[r2];
}

// ---------------------------------------------------------------------------
// Causal flash attention, fp32 (unchanged — known correct from Round 1)
// ---------------------------------------------------------------------------
#define AQ   128
#define AK   64
#define SSTR 65
#define L2E  1.44269504088896341f

#define ATTN_SMEM_FLOATS (AK*RKD + AK*HD + AQ*SSTR)
#define ATTN_SMEM_BYTES  (ATTN_SMEM_FLOATS * 4)

__global__ __launch_bounds__(AQ)
void attn_kernel()
{
    extern __shared__ float sm[];
    float* Ks = sm;
    float* Vs = sm + AK * RKD;
    float* Ss = Vs + AK * HD;

    const int bh  = blockIdx.y;
    const int b   = bh / NH;
    const int h   = bh % NH;
    const int qt  = blockIdx.x;
    const int tid = threadIdx.x;
    const int qi  = qt * AQ + tid;

    float q[RKD];
    const float* qrow = &g_qk[((size_t)bh * SEQ + qi) * RKD];
    #pragma unroll
    for (int d = 0; d < RKD; d++) q[d] = qrow[d];

    float o[HD];
    #pragma unroll
    for (int d = 0; d < HD; d++) o[d] = 0.f;
    float mrun = -1e30f, lsum = 0.f;

    const int ktiles = 2 * qt + 2;

    for (int kt = 0; kt < ktiles; kt++) {
        const int j0 = kt * AK;

        __syncthreads();
        for (int i = tid; i < AK * RKD / 4; i += AQ) {
            const int row = i >> 3, c = (i & 7) * 4;
            *reinterpret_cast<float4*>(&Ks[row * RKD + c]) =
                *reinterpret_cast<const float4*>(&g_kk[((size_t)bh * SEQ + j0 + row) * RKD + c]);
        }
        for (int i = tid; i < AK * HD / 4; i += AQ) {
            const int row = i >> 4, c = (i & 15) * 4;
            *reinterpret_cast<float4*>(&Vs[row * HD + c]) =
                *reinterpret_cast<const float4*>(&g_v[((size_t)(b * SEQ + j0 + row)) * CH + h * HD + c]);
        }
        __syncthreads();

        if (j0 <= qi) {
            float* srow = &Ss[tid * SSTR];
            float mt = -1e30f;
            #pragma unroll 4
            for (int j = 0; j < AK; j++) {
                float s = -1e30f;
                if (j0 + j <= qi) {
                    s = 0.f;
                    const float* krow = &Ks[j * RKD];
                    #pragma unroll
                    for (int d = 0; d < RKD; d++) s = fmaf(q[d], krow[d], s);
                }
                srow[j] = s;
                mt = fmaxf(mt, s);
            }
            const float mnew = fmaxf(mrun, mt);
            const float corr = exp2f((mrun - mnew) * L2E);
            lsum *= corr;
            #pragma unroll
            for (int d = 0; d < HD; d++) o[d] *= corr;

            for (int j = 0; j < AK; j++) {
                const float p = exp2f((srow[j] - mnew) * L2E);
                lsum += p;
                const float* vrow = &Vs[j * HD];
                #pragma unroll
                for (int d = 0; d < HD; d++) o[d] = fmaf(p, vrow[d], o[d]);
            }
            mrun = mnew;
        }
    }

    const float inv = 1.f / lsum;
    float* dst = &g_ao[((size_t)(b * SEQ + qi)) * CH + h * HD];
    #pragma unroll
    for (int d = 0; d < HD; d++) dst[d] = o[d] * inv;
}

// ---------------------------------------------------------------------------
// Launch
// ---------------------------------------------------------------------------
extern "C" void kernel_launch(void* const* d_in, const int* in_sizes, int n_in,
                              void* d_out, int out_size)
{
    const float* x   = (const float*)d_in[0];
    const float* Wq1 = (const float*)d_in[1];
    const float* Wk1 = (const float*)d_in[2];
    const float* Wq2 = (const float*)d_in[3];
    const float* Wk2 = (const float*)d_in[4];
    const float* Wv  = (const float*)d_in[5];
    const float* Wo  = (const float*)d_in[6];
    const float* bo  = (const float*)d_in[7];
    float* out = (float*)d_out;

    cudaFuncSetAttribute(attn_kernel, cudaFuncAttributeMaxDynamicSharedMemorySize,
                         ATTN_SMEM_BYTES);

    __nv_bfloat16 *xh, *xl, *wch, *wcl, *wvh, *wvl, *woh, *wol, *aoh, *aol;
    float *proj, *v, *ao;
    cudaGetSymbolAddress((void**)&xh,  g_xh);
    cudaGetSymbolAddress((void**)&xl,  g_xl);
    cudaGetSymbolAddress((void**)&wch, g_wch);
    cudaGetSymbolAddress((void**)&wcl, g_wcl);
    cudaGetSymbolAddress((void**)&wvh, g_wvh);
    cudaGetSymbolAddress((void**)&wvl, g_wvl);
    cudaGetSymbolAddress((void**)&woh, g_woh);
    cudaGetSymbolAddress((void**)&wol, g_wol);
    cudaGetSymbolAddress((void**)&aoh, g_aoh);
    cudaGetSymbolAddress((void**)&aol, g_aol);
    cudaGetSymbolAddress((void**)&proj, g_proj);
    cudaGetSymbolAddress((void**)&v,   g_v);
    cudaGetSymbolAddress((void**)&ao,  g_ao);

    const int SB = 256;
    // splits: x, concat weights (Wq1|Wk1|Wq2|Wk2), Wv, Wo
    split_kernel<<<(MROWS*CH + SB-1)/SB, SB>>>(x, xh, xl, MROWS*CH);
    split_kernel<<<(64*CH + SB-1)/SB, SB>>>(Wq1, wch,          wcl,          64*CH);
    split_kernel<<<(64*CH + SB-1)/SB, SB>>>(Wk1, wch +  64*CH, wcl +  64*CH, 64*CH);
    split_kernel<<<(128*CH + SB-1)/SB, SB>>>(Wq2, wch + 128*CH, wcl + 128*CH, 128*CH);
    split_kernel<<<(128*CH + SB-1)/SB, SB>>>(Wk2, wch + 256*CH, wcl + 256*CH, 128*CH);
    split_kernel<<<(CH*CH + SB-1)/SB, SB>>>(Wv, wvh, wvl, CH*CH);
    split_kernel<<<(CH*CH + SB-1)/SB, SB>>>(Wo, woh, wol, CH*CH);

    // fused projections: [4096 x 384] = x @ Wcat^T
    gemm_bf16x3<<<dim3(MROWS/TM, PROJC/TN), GT>>>(xh, xl, wch, wcl, nullptr,
                                                  proj, PROJC, CH);
    // V: [4096 x 1024] = x @ Wv^T
    gemm_bf16x3<<<dim3(MROWS/TM, CH/TN), GT>>>(xh, xl, wvh, wvl, nullptr,
                                               v, CH, CH);

    form_qkkk_kernel<<<(MROWS*NH + SB-1)/SB, SB>>>();

    attn_kernel<<<dim3(SEQ/AQ, BATCH*NH), AQ, ATTN_SMEM_BYTES>>>();

    // split attention output, then out = ao @ Wo^T + bo
    split_kernel<<<(MROWS*CH + SB-1)/SB, SB>>>(ao, aoh, aol, MROWS*CH);
    gemm_bf16x3<<<dim3(MROWS/TM, CH/TN), GT>>>(aoh, aol, woh, wol, bo,
                                               out, CH, CH);
}

// round 7
// speedup vs baseline: 3.0370x; 2.0834x over previous
#include <cuda_runtime.h>
#include <cuda_bf16.h>
#include <math.h>
#include <stdint.h>

// ---------------------------------------------------------------------------
// Problem constants (B=2, N=2048, C=1024, H=16, R1=4, R2=8, HEAD_DIM=64)
// ---------------------------------------------------------------------------
#define BATCH 2
#define SEQ   2048
#define CH    1024
#define NH    16
#define RR1   4
#define RR2   8
#define HD    64
#define RKD   32              // R1*R2: effective qk head dim
#define MROWS (BATCH*SEQ)     // 4096
#define PROJC 384             // 64+64+128+128 concatenated projection outputs
#define BH    (BATCH*NH)      // 32

#define L2E  1.44269504088896341f
__device__ __constant__ float kQSCALE = 0.17677669529663687f * 1.44269504088896341f;

// ---------------------------------------------------------------------------
// Scratch (device globals; no allocation allowed)
// ---------------------------------------------------------------------------
__device__ __nv_bfloat16 g_xh [MROWS * CH];
__device__ __nv_bfloat16 g_xl [MROWS * CH];
__device__ __nv_bfloat16 g_wch[PROJC * CH];
__device__ __nv_bfloat16 g_wcl[PROJC * CH];
__device__ __nv_bfloat16 g_wvh[CH * CH];
__device__ __nv_bfloat16 g_wvl[CH * CH];
__device__ __nv_bfloat16 g_woh[CH * CH];
__device__ __nv_bfloat16 g_wol[CH * CH];
__device__ __nv_bfloat16 g_aoh[MROWS * CH];
__device__ __nv_bfloat16 g_aol[MROWS * CH];

__device__ float g_proj[MROWS * PROJC];
__device__ float g_v  [MROWS * CH];
__device__ float g_ao [MROWS * CH];

// attention operands, per-head layouts, bf16 hi/lo
__device__ __nv_bfloat16 g_qkh[(size_t)BH * SEQ * RKD];   // [bh][n][32], scaled by SCALE*L2E
__device__ __nv_bfloat16 g_qkl[(size_t)BH * SEQ * RKD];
__device__ __nv_bfloat16 g_kkh[(size_t)BH * SEQ * RKD];
__device__ __nv_bfloat16 g_kkl[(size_t)BH * SEQ * RKD];
__device__ __nv_bfloat16 g_vth[(size_t)BH * HD * SEQ];    // [bh][d][n] (V transposed)
__device__ __nv_bfloat16 g_vtl[(size_t)BH * HD * SEQ];

// ---------------------------------------------------------------------------
// Warp-MMA helpers
// ---------------------------------------------------------------------------
__device__ __forceinline__ uint32_t smem_u32(const void* p) {
    uint32_t a;
    asm("{ .reg .u64 t; cvta.to.shared.u64 t, %1; cvt.u32.u64 %0, t; }"
        : "=r"(a) : "l"(p));
    return a;
}

__device__ __forceinline__ void ldsm_x4(uint32_t addr, uint32_t& r0, uint32_t& r1,
                                        uint32_t& r2, uint32_t& r3) {
    asm volatile("ldmatrix.sync.aligned.m8n8.x4.shared.b16 {%0,%1,%2,%3}, [%4];"
                 : "=r"(r0), "=r"(r1), "=r"(r2), "=r"(r3) : "r"(addr));
}

__device__ __forceinline__ void mma16816(float* c, uint32_t a0, uint32_t a1,
                                         uint32_t a2, uint32_t a3,
                                         uint32_t b0, uint32_t b1) {
    asm volatile(
        "mma.sync.aligned.m16n8k16.row.col.f32.bf16.bf16.f32 "
        "{%0,%1,%2,%3}, {%4,%5,%6,%7}, {%8,%9}, {%0,%1,%2,%3};"
        : "+f"(c[0]), "+f"(c[1]), "+f"(c[2]), "+f"(c[3])
        : "r"(a0), "r"(a1), "r"(a2), "r"(a3), "r"(b0), "r"(b1));
}

__device__ __forceinline__ uint32_t pack_bf16(float x, float y) {
    __nv_bfloat162 t = __floats2bfloat162_rn(x, y);  // x -> low half
    return *reinterpret_cast<uint32_t*>(&t);
}

// ---------------------------------------------------------------------------
// Split fp32 -> bf16 hi/lo
// ---------------------------------------------------------------------------
__global__ void split_kernel(const float* __restrict__ src,
                             __nv_bfloat16* __restrict__ hi,
                             __nv_bfloat16* __restrict__ lo, int n)
{
    int i = blockIdx.x * blockDim.x + threadIdx.x;
    if (i < n) {
        float v = src[i];
        __nv_bfloat16 h = __float2bfloat16(v);
        hi[i] = h;
        lo[i] = __float2bfloat16(v - __bfloat162float(h));
    }
}

// ---------------------------------------------------------------------------
// bf16x3 NT GEMM (unchanged — validated Round 5)
// ---------------------------------------------------------------------------
#define TM 128
#define TN 128
#define TKC 32
#define GT 256
#define SPAD 40

__global__ __launch_bounds__(GT)
void gemm_bf16x3(const __nv_bfloat16* __restrict__ Ahi,
                 const __nv_bfloat16* __restrict__ Alo,
                 const __nv_bfloat16* __restrict__ Bhi,
                 const __nv_bfloat16* __restrict__ Blo,
                 const float* __restrict__ bias,
                 float* __restrict__ C, int Nc, int K)
{
    __shared__ __nv_bfloat16 sAh[TM * SPAD];
    __shared__ __nv_bfloat16 sAl[TM * SPAD];
    __shared__ __nv_bfloat16 sBh[TN * SPAD];
    __shared__ __nv_bfloat16 sBl[TN * SPAD];

    const int tid  = threadIdx.x;
    const int wid  = tid >> 5;
    const int lane = tid & 31;
    const int wm   = wid >> 2;
    const int wn   = wid & 3;

    const int m0 = blockIdx.x * TM;
    const int n0 = blockIdx.y * TN;

    float acc[4][4][4] = {};

    const int a_r = lane & 15, a_c = (lane >> 4) * 8;
    const int b_r = (lane & 7) + ((lane >> 4) << 3), b_c = ((lane >> 3) & 1) * 8;

    const uint32_t sAh_u = smem_u32(sAh), sAl_u = smem_u32(sAl);
    const uint32_t sBh_u = smem_u32(sBh), sBl_u = smem_u32(sBl);

    for (int k0 = 0; k0 < K; k0 += TKC) {
        __syncthreads();
        #pragma unroll
        for (int i = tid; i < TM * 4; i += GT) {
            const int row = i >> 2, seg = (i & 3) * 8;
            const int so = row * SPAD + seg;
            const size_t ga = (size_t)(m0 + row) * K + k0 + seg;
            const size_t gb = (size_t)(n0 + row) * K + k0 + seg;
            *reinterpret_cast<float4*>(&sAh[so]) = *reinterpret_cast<const float4*>(&Ahi[ga]);
            *reinterpret_cast<float4*>(&sAl[so]) = *reinterpret_cast<const float4*>(&Alo[ga]);
            *reinterpret_cast<float4*>(&sBh[so]) = *reinterpret_cast<const float4*>(&Bhi[gb]);
            *reinterpret_cast<float4*>(&sBl[so]) = *reinterpret_cast<const float4*>(&Blo[gb]);
        }
        __syncthreads();

        #pragma unroll
        for (int kp = 0; kp < 2; kp++) {
            const int kb = kp * 16;
            uint32_t ah[4][4], al[4][4], bh[2][4], bl[2][4];

            #pragma unroll
            for (int mt = 0; mt < 4; mt++) {
                const uint32_t off =
                    (uint32_t)((wm * 64 + mt * 16 + a_r) * SPAD + kb + a_c) * 2;
                ldsm_x4(sAh_u + off, ah[mt][0], ah[mt][1], ah[mt][2], ah[mt][3]);
                ldsm_x4(sAl_u + off, al[mt][0], al[mt][1], al[mt][2], al[mt][3]);
            }
            #pragma unroll
            for (int ng = 0; ng < 2; ng++) {
                const uint32_t off =
                    (uint32_t)((wn * 32 + ng * 16 + b_r) * SPAD + kb + b_c) * 2;
                ldsm_x4(sBh_u + off, bh[ng][0], bh[ng][1], bh[ng][2], bh[ng][3]);
                ldsm_x4(sBl_u + off, bl[ng][0], bl[ng][1], bl[ng][2], bl[ng][3]);
            }

            #pragma unroll
            for (int mt = 0; mt < 4; mt++) {
                #pragma unroll
                for (int nt = 0; nt < 4; nt++) {
                    const int ng = nt >> 1, hp = (nt & 1) * 2;
                    mma16816(acc[mt][nt], ah[mt][0], ah[mt][1], ah[mt][2], ah[mt][3],
                             bh[ng][hp], bh[ng][hp + 1]);
                    mma16816(acc[mt][nt], ah[mt][0], ah[mt][1], ah[mt][2], ah[mt][3],
                             bl[ng][hp], bl[ng][hp + 1]);
                    mma16816(acc[mt][nt], al[mt][0], al[mt][1], al[mt][2], al[mt][3],
                             bh[ng][hp], bh[ng][hp + 1]);
                }
            }
        }
    }

    const int er = lane >> 2, ec = (lane & 3) * 2;
    #pragma unroll
    for (int mt = 0; mt < 4; mt++) {
        #pragma unroll
        for (int nt = 0; nt < 4; nt++) {
            const int row = m0 + wm * 64 + mt * 16 + er;
            const int col = n0 + wn * 32 + nt * 8 + ec;
            float b0 = bias ? bias[col] : 0.f;
            float b1 = bias ? bias[col + 1] : 0.f;
            C[(size_t)row * Nc + col]           = acc[mt][nt][0] + b0;
            C[(size_t)row * Nc + col + 1]       = acc[mt][nt][1] + b1;
            C[(size_t)(row + 8) * Nc + col]     = acc[mt][nt][2] + b0;
            C[(size_t)(row + 8) * Nc + col + 1] = acc[mt][nt][3] + b1;
        }
    }
}

// ---------------------------------------------------------------------------
// Form qk (scaled by SCALE*L2E) / kk outer products -> bf16 hi/lo, per head
// ---------------------------------------------------------------------------
__global__ void form_qkkk_kernel()
{
    const int idx = blockIdx.x * blockDim.x + threadIdx.x;
    if (idx >= MROWS * NH) return;
    const int h  = idx % NH;
    const int bn = idx / NH;
    const int b  = bn / SEQ;
    const int n  = bn % SEQ;

    const float* pr = &g_proj[(size_t)bn * PROJC];
    float a1[RR1], a2[RR2];
    #pragma unroll
    for (int r = 0; r < RR1; r++) a1[r] = pr[h * RR1 + r];
    #pragma unroll
    for (int r = 0; r < RR2; r++) a2[r] = pr[128 + h * RR2 + r];

    const size_t base = (((size_t)b * NH + h) * SEQ + n) * RKD;
    #pragma unroll
    for (int r1 = 0; r1 < RR1; r1++)
        #pragma unroll
        for (int r2 = 0; r2 < RR2; r2++) {
            float v = a1[r1] * a2[r2] * kQSCALE;
            __nv_bfloat16 hh = __float2bfloat16(v);
            g_qkh[base + r1 * RR2 + r2] = hh;
            g_qkl[base + r1 * RR2 + r2] = __float2bfloat16(v - __bfloat162float(hh));
        }

    #pragma unroll
    for (int r = 0; r < RR1; r++) a1[r] = pr[64 + h * RR1 + r];
    #pragma unroll
    for (int r = 0; r < RR2; r++) a2[r] = pr[256 + h * RR2 + r];

    #pragma unroll
    for (int r1 = 0; r1 < RR1; r1++)
        #pragma unroll
        for (int r2 = 0; r2 < RR2; r2++) {
            float v = a1[r1] * a2[r2];
            __nv_bfloat16 hh = __float2bfloat16(v);
            g_kkh[base + r1 * RR2 + r2] = hh;
            g_kkl[base + r1 * RR2 + r2] = __float2bfloat16(v - __bfloat162float(hh));
        }
}

// ---------------------------------------------------------------------------
// V transpose+split: g_v[bn][CH] -> g_vt{h,l}[bh][d][n]
// Grid: (SEQ/64, BH), 256 threads. smem tile 64n x 64d, 65-float row pad.
// FIX R6: gmem float4 -> registers -> 4 SCALAR smem stores (65-stride rows
// are not 16B-aligned; the float4 smem store faulted with misaligned address).
// ---------------------------------------------------------------------------
__global__ __launch_bounds__(256)
void vt_convert_kernel()
{
    __shared__ float sm[64][65];
    const int bh = blockIdx.y;
    const int b = bh / NH, h = bh % NH;
    const int n0 = blockIdx.x * 64;
    const int tid = threadIdx.x;

    for (int i = tid; i < 64 * 16; i += 256) {
        const int n = i >> 4, seg = (i & 15) * 4;
        const float4 v4 = *reinterpret_cast<const float4*>(
            &g_v[((size_t)(b * SEQ + n0 + n)) * CH + h * HD + seg]);
        sm[n][seg + 0] = v4.x;
        sm[n][seg + 1] = v4.y;
        sm[n][seg + 2] = v4.z;
        sm[n][seg + 3] = v4.w;
    }
    __syncthreads();

    for (int i = tid; i < 64 * 64; i += 256) {
        const int d = i >> 6, n = i & 63;
        const float v = sm[n][d];
        const __nv_bfloat16 hh = __float2bfloat16(v);
        const size_t o = ((size_t)bh * HD + d) * SEQ + n0 + n;
        g_vth[o] = hh;
        g_vtl[o] = __float2bfloat16(v - __bfloat162float(hh));
    }
}

// ---------------------------------------------------------------------------
// MMA flash attention (causal). Block: 64 q-rows, 4 warps x 16 rows.
// K tiles of 64. S via bf16x3 QK^T; online softmax in regs; PV via bf16x3.
// ---------------------------------------------------------------------------
#define FQ 64
#define FK 64
#define KSP 40        // smem row stride for Q/K (32 + 8 pad), mult of 8 -> 16B ok
#define VSP 72        // smem row stride for Vt (64 + 8 pad), mult of 8 -> 16B ok

__global__ __launch_bounds__(128)
void attn_mma_kernel()
{
    __shared__ __nv_bfloat16 sQh[FQ * KSP], sQl[FQ * KSP];
    __shared__ __nv_bfloat16 sKh[FK * KSP], sKl[FK * KSP];
    __shared__ __nv_bfloat16 sVh[HD * VSP], sVl[HD * VSP];

    const int bh  = blockIdx.y;
    const int b   = bh / NH, h = bh % NH;
    const int qt  = blockIdx.x;
    const int q0  = qt * FQ;
    const int tid = threadIdx.x;
    const int wid = tid >> 5;
    const int lane = tid & 31;

    const __nv_bfloat16* qkh = &g_qkh[(size_t)bh * SEQ * RKD];
    const __nv_bfloat16* qkl = &g_qkl[(size_t)bh * SEQ * RKD];
    const __nv_bfloat16* kkh = &g_kkh[(size_t)bh * SEQ * RKD];
    const __nv_bfloat16* kkl = &g_kkl[(size_t)bh * SEQ * RKD];
    const __nv_bfloat16* vth = &g_vth[(size_t)bh * HD * SEQ];
    const __nv_bfloat16* vtl = &g_vtl[(size_t)bh * HD * SEQ];

    // stage Q tile (persistent)
    for (int i = tid; i < FQ * 4; i += 128) {
        const int row = i >> 2, seg = (i & 3) * 8;
        *reinterpret_cast<float4*>(&sQh[row * KSP + seg]) =
            *reinterpret_cast<const float4*>(&qkh[(size_t)(q0 + row) * RKD + seg]);
        *reinterpret_cast<float4*>(&sQl[row * KSP + seg]) =
            *reinterpret_cast<const float4*>(&qkl[(size_t)(q0 + row) * RKD + seg]);
    }
    __syncthreads();

    const int a_r = lane & 15, a_c = (lane >> 4) * 8;
    const int b_r = (lane & 7) + ((lane >> 4) << 3), b_c = ((lane >> 3) & 1) * 8;

    const uint32_t sQh_u = smem_u32(sQh), sQl_u = smem_u32(sQl);
    const uint32_t sKh_u = smem_u32(sKh), sKl_u = smem_u32(sKl);
    const uint32_t sVh_u = smem_u32(sVh), sVl_u = smem_u32(sVl);

    uint32_t qh[2][4], ql[2][4];
    #pragma unroll
    for (int kc = 0; kc < 2; kc++) {
        const uint32_t off = (uint32_t)((wid * 16 + a_r) * KSP + kc * 16 + a_c) * 2;
        ldsm_x4(sQh_u + off, qh[kc][0], qh[kc][1], qh[kc][2], qh[kc][3]);
        ldsm_x4(sQl_u + off, ql[kc][0], ql[kc][1], ql[kc][2], ql[kc][3]);
    }

    float Od[8][4] = {};
    float m0 = -1e30f, m1 = -1e30f, l0 = 0.f, l1 = 0.f;
    const int myrow = q0 + wid * 16 + (lane >> 2);

    for (int kt = 0; kt <= qt; kt++) {
        const int j0 = kt * FK;

        __syncthreads();
        for (int i = tid; i < FK * 4; i += 128) {
            const int row = i >> 2, seg = (i & 3) * 8;
            *reinterpret_cast<float4*>(&sKh[row * KSP + seg]) =
                *reinterpret_cast<const float4*>(&kkh[(size_t)(j0 + row) * RKD + seg]);
            *reinterpret_cast<float4*>(&sKl[row * KSP + seg]) =
                *reinterpret_cast<const float4*>(&kkl[(size_t)(j0 + row) * RKD + seg]);
        }
        for (int i = tid; i < HD * 8; i += 128) {
            const int row = i >> 3, seg = (i & 7) * 8;
            *reinterpret_cast<float4*>(&sVh[row * VSP + seg]) =
                *reinterpret_cast<const float4*>(&vth[(size_t)row * SEQ + j0 + seg]);
            *reinterpret_cast<float4*>(&sVl[row * VSP + seg]) =
                *reinterpret_cast<const float4*>(&vtl[(size_t)row * SEQ + j0 + seg]);
        }
        __syncthreads();

        // ---- S = QK^T (bf16x3) ----
        float S[8][4];
        #pragma unroll
        for (int nt = 0; nt < 8; nt++)
            #pragma unroll
            for (int e = 0; e < 4; e++) S[nt][e] = 0.f;

        #pragma unroll
        for (int kc = 0; kc < 2; kc++) {
            #pragma unroll
            for (int g = 0; g < 4; g++) {
                uint32_t kb[4], kl[4];
                const uint32_t off = (uint32_t)((g * 16 + b_r) * KSP + kc * 16 + b_c) * 2;
                ldsm_x4(sKh_u + off, kb[0], kb[1], kb[2], kb[3]);
                ldsm_x4(sKl_u + off, kl[0], kl[1], kl[2], kl[3]);
                #pragma unroll
                for (int t = 0; t < 2; t++) {
                    const int nt = g * 2 + t, hp = t * 2;
                    mma16816(S[nt], qh[kc][0], qh[kc][1], qh[kc][2], qh[kc][3],
                             kb[hp], kb[hp + 1]);
                    mma16816(S[nt], qh[kc][0], qh[kc][1], qh[kc][2], qh[kc][3],
                             kl[hp], kl[hp + 1]);
                    mma16816(S[nt], ql[kc][0], ql[kc][1], ql[kc][2], ql[kc][3],
                             kb[hp], kb[hp + 1]);
                }
            }
        }

        // ---- causal mask on diagonal tile ----
        if (kt == qt) {
            #pragma unroll
            for (int nt = 0; nt < 8; nt++) {
                const int col = j0 + nt * 8 + (lane & 3) * 2;
                if (col     > myrow)     S[nt][0] = -1e30f;
                if (col + 1 > myrow)     S[nt][1] = -1e30f;
                if (col     > myrow + 8) S[nt][2] = -1e30f;
                if (col + 1 > myrow + 8) S[nt][3] = -1e30f;
            }
        }

        // ---- online softmax (rows myrow, myrow+8) ----
        float r0 = -1e30f, r1 = -1e30f;
        #pragma unroll
        for (int nt = 0; nt < 8; nt++) {
            r0 = fmaxf(r0, fmaxf(S[nt][0], S[nt][1]));
            r1 = fmaxf(r1, fmaxf(S[nt][2], S[nt][3]));
        }
        r0 = fmaxf(r0, __shfl_xor_sync(0xffffffff, r0, 1));
        r0 = fmaxf(r0, __shfl_xor_sync(0xffffffff, r0, 2));
        r1 = fmaxf(r1, __shfl_xor_sync(0xffffffff, r1, 1));
        r1 = fmaxf(r1, __shfl_xor_sync(0xffffffff, r1, 2));

        const float mn0 = fmaxf(m0, r0), mn1 = fmaxf(m1, r1);
        const float c0 = exp2f(m0 - mn0), c1 = exp2f(m1 - mn1);
        m0 = mn0; m1 = mn1;

        float s0 = 0.f, s1 = 0.f;
        #pragma unroll
        for (int nt = 0; nt < 8; nt++) {
            S[nt][0] = exp2f(S[nt][0] - mn0);
            S[nt][1] = exp2f(S[nt][1] - mn0);
            S[nt][2] = exp2f(S[nt][2] - mn1);
            S[nt][3] = exp2f(S[nt][3] - mn1);
            s0 += S[nt][0] + S[nt][1];
            s1 += S[nt][2] + S[nt][3];
        }
        l0 = l0 * c0 + s0;
        l1 = l1 * c1 + s1;

        #pragma unroll
        for (int nt = 0; nt < 8; nt++) {
            Od[nt][0] *= c0; Od[nt][1] *= c0;
            Od[nt][2] *= c1; Od[nt][3] *= c1;
        }

        // ---- O += P * V (bf16x3) ----
        #pragma unroll
        for (int kc = 0; kc < 4; kc++) {
            uint32_t pa[4], pl[4];
            {
                const float x0 = S[2 * kc][0],     y0 = S[2 * kc][1];
                const float x1 = S[2 * kc][2],     y1 = S[2 * kc][3];
                const float x2 = S[2 * kc + 1][0], y2 = S[2 * kc + 1][1];
                const float x3 = S[2 * kc + 1][2], y3 = S[2 * kc + 1][3];
                pa[0] = pack_bf16(x0, y0); pa[1] = pack_bf16(x1, y1);
                pa[2] = pack_bf16(x2, y2); pa[3] = pack_bf16(x3, y3);
                __nv_bfloat162 h0 = *reinterpret_cast<__nv_bfloat162*>(&pa[0]);
                __nv_bfloat162 h1 = *reinterpret_cast<__nv_bfloat162*>(&pa[1]);
                __nv_bfloat162 h2 = *reinterpret_cast<__nv_bfloat162*>(&pa[2]);
                __nv_bfloat162 h3 = *reinterpret_cast<__nv_bfloat162*>(&pa[3]);
                pl[0] = pack_bf16(x0 - __bfloat162float(h0.x), y0 - __bfloat162float(h0.y));
                pl[1] = pack_bf16(x1 - __bfloat162float(h1.x), y1 - __bfloat162float(h1.y));
                pl[2] = pack_bf16(x2 - __bfloat162float(h2.x), y2 - __bfloat162float(h2.y));
                pl[3] = pack_bf16(x3 - __bfloat162float(h3.x), y3 - __bfloat162float(h3.y));
            }
            #pragma unroll
            for (int g = 0; g < 4; g++) {
                uint32_t vb[4], vl[4];
                const uint32_t off = (uint32_t)((g * 16 + b_r) * VSP + kc * 16 + b_c) * 2;
                ldsm_x4(sVh_u + off, vb[0], vb[1], vb[2], vb[3]);
                ldsm_x4(sVl_u + off, vl[0], vl[1], vl[2], vl[3]);
                #pragma unroll
                for (int t = 0; t < 2; t++) {
                    const int nt = g * 2 + t, hp = t * 2;
                    mma16816(Od[nt], pa[0], pa[1], pa[2], pa[3], vb[hp], vb[hp + 1]);
                    mma16816(Od[nt], pl[0], pl[1], pl[2], pl[3], vb[hp], vb[hp + 1]);
                    mma16816(Od[nt], pa[0], pa[1], pa[2], pa[3], vl[hp], vl[hp + 1]);
                }
            }
        }
    }

    // ---- finalize ----
    l0 += __shfl_xor_sync(0xffffffff, l0, 1);
    l0 += __shfl_xor_sync(0xffffffff, l0, 2);
    l1 += __shfl_xor_sync(0xffffffff, l1, 1);
    l1 += __shfl_xor_sync(0xffffffff, l1, 2);
    const float i0 = 1.f / l0, i1 = 1.f / l1;

    float* dst0 = &g_ao[((size_t)(b * SEQ + myrow)) * CH + h * HD];
    float* dst1 = dst0 + (size_t)8 * CH;
    #pragma unroll
    for (int nt = 0; nt < 8; nt++) {
        const int d = nt * 8 + (lane & 3) * 2;
        dst0[d]     = Od[nt][0] * i0;
        dst0[d + 1] = Od[nt][1] * i0;
        dst1[d]     = Od[nt][2] * i1;
        dst1[d + 1] = Od[nt][3] * i1;
    }
}

// ---------------------------------------------------------------------------
// Launch
// ---------------------------------------------------------------------------
extern "C" void kernel_launch(void* const* d_in, const int* in_sizes, int n_in,
                              void* d_out, int out_size)
{
    const float* x   = (const float*)d_in[0];
    const float* Wq1 = (const float*)d_in[1];
    const float* Wk1 = (const float*)d_in[2];
    const float* Wq2 = (const float*)d_in[3];
    const float* Wk2 = (const float*)d_in[4];
    const float* Wv  = (const float*)d_in[5];
    const float* Wo  = (const float*)d_in[6];
    const float* bo  = (const float*)d_in[7];
    float* out = (float*)d_out;

    __nv_bfloat16 *xh, *xl, *wch, *wcl, *wvh, *wvl, *woh, *wol, *aoh, *aol;
    float *proj, *v, *ao;
    cudaGetSymbolAddress((void**)&xh,  g_xh);
    cudaGetSymbolAddress((void**)&xl,  g_xl);
    cudaGetSymbolAddress((void**)&wch, g_wch);
    cudaGetSymbolAddress((void**)&wcl, g_wcl);
    cudaGetSymbolAddress((void**)&wvh, g_wvh);
    cudaGetSymbolAddress((void**)&wvl, g_wvl);
    cudaGetSymbolAddress((void**)&woh, g_woh);
    cudaGetSymbolAddress((void**)&wol, g_wol);
    cudaGetSymbolAddress((void**)&aoh, g_aoh);
    cudaGetSymbolAddress((void**)&aol, g_aol);
    cudaGetSymbolAddress((void**)&proj, g_proj);
    cudaGetSymbolAddress((void**)&v,   g_v);
    cudaGetSymbolAddress((void**)&ao,  g_ao);

    const int SB = 256;
    split_kernel<<<(MROWS*CH + SB-1)/SB, SB>>>(x, xh, xl, MROWS*CH);
    split_kernel<<<(64*CH + SB-1)/SB, SB>>>(Wq1, wch,          wcl,          64*CH);
    split_kernel<<<(64*CH + SB-1)/SB, SB>>>(Wk1, wch +  64*CH, wcl +  64*CH, 64*CH);
    split_kernel<<<(128*CH + SB-1)/SB, SB>>>(Wq2, wch + 128*CH, wcl + 128*CH, 128*CH);
    split_kernel<<<(128*CH + SB-1)/SB, SB>>>(Wk2, wch + 256*CH, wcl + 256*CH, 128*CH);
    split_kernel<<<(CH*CH + SB-1)/SB, SB>>>(Wv, wvh, wvl, CH*CH);
    split_kernel<<<(CH*CH + SB-1)/SB, SB>>>(Wo, woh, wol, CH*CH);

    gemm_bf16x3<<<dim3(MROWS/TM, PROJC/TN), GT>>>(xh, xl, wch, wcl, nullptr,
                                                  proj, PROJC, CH);
    gemm_bf16x3<<<dim3(MROWS/TM, CH/TN), GT>>>(xh, xl, wvh, wvl, nullptr,
                                               v, CH, CH);

    form_qkkk_kernel<<<(MROWS*NH + SB-1)/SB, SB>>>();
    vt_convert_kernel<<<dim3(SEQ/64, BH), 256>>>();

    attn_mma_kernel<<<dim3(SEQ/FQ, BH), 128>>>();

    split_kernel<<<(MROWS*CH + SB-1)/SB, SB>>>(ao, aoh, aol, MROWS*CH);
    gemm_bf16x3<<<dim3(MROWS/TM, CH/TN), GT>>>(aoh, aol, woh, wol, bo,
                                               out, CH, CH);
}